// round 9
// baseline (speedup 1.0000x reference)
#include <cuda_runtime.h>
#include <cstdint>
#include <cstddef>

// ---------------------------------------------------------------- constants
#define NB     128
#define NTOK   1369
#define DINOD  384
#define CLIPD  512
#define NH     8
#define HD     64
#define TN     48          // tokens per tile
#define NT     29          // ceil(1369/48)
#define DPITCH 388         // dino tile row pitch (floats), 16B-aligned, bank-skewed
#define QPITCH 392         // qk row pitch
#define PSP    52          // p/logits row pitch

// dynamic smem layout for k_main (float offsets)
#define OFF_DS   0
#define OFF_QK   (2*TN*DPITCH)            // 37248
#define OFF_LP   (OFF_QK + NH*QPITCH)     // 40384
#define OFF_PS   (OFF_LP + 12*NH*TN)      // 44992
#define OFF_OUTS (OFF_PS + NH*PSP)        // 45408
#define OFF_MRUN (OFF_OUTS + CLIPD)       // 45920
#define OFF_LRUN (OFF_MRUN + NH)
#define OFF_ALPH (OFF_LRUN + NH)
#define OFF_RED  (OFF_ALPH + NH)
#define OFF_RED2 (OFF_RED + 12)
#define OFF_STAT (OFF_RED2 + 12)
#define SMEM_FLOATS (OFF_STAT + 2)
#define SMEM_BYTES  (SMEM_FLOATS * 4)

// device scratch (no allocation APIs allowed)
__device__ float g_Q[NB * CLIPD];
__device__ float g_qk[NB * NH * DINOD];

static __device__ __forceinline__ void cp16(float* sdst, const float* gsrc, bool valid) {
    uint32_t s = (uint32_t)__cvta_generic_to_shared(sdst);
    int sz = valid ? 16 : 0;     // sz=0 -> zero-fill destination
    asm volatile("cp.async.cg.shared.global [%0], [%1], 16, %2;\n"
                 :: "r"(s), "l"(gsrc), "r"(sz) : "memory");
}

// ---------------------------------------------------------------------------
// P1: Q[b, c] = clip[b,:] @ Wq[:, c] + bq[c]   (128x512 @ 512x512)
// grid (16, 4): x = 32-wide c tile, y = 32-wide b tile. 256 threads, 2x2/thr.
// ---------------------------------------------------------------------------
__global__ void __launch_bounds__(256)
k_qproj(const float* __restrict__ clip, const float* __restrict__ Wq,
        const float* __restrict__ bq) {
    __shared__ float As[32 * 33];
    __shared__ float Bs[32 * 33];
    const int t  = threadIdx.x;
    const int h0 = blockIdx.x * 32;
    const int b0 = blockIdx.y * 32;
    const int tr = t >> 4;    // 0..15
    const int tc = t & 15;    // 0..15
    float acc00 = 0.f, acc01 = 0.f, acc10 = 0.f, acc11 = 0.f;

    for (int kc = 0; kc < 16; ++kc) {
        #pragma unroll
        for (int i = 0; i < 4; ++i) {
            int flat = t + 256 * i;      // < 1024
            int r = flat >> 5, c = flat & 31;
            As[r * 33 + c] = clip[(b0 + r) * CLIPD + kc * 32 + c];
            Bs[r * 33 + c] = Wq[(kc * 32 + r) * CLIPD + h0 + c];
        }
        __syncthreads();
        #pragma unroll
        for (int k = 0; k < 32; ++k) {
            float a0 = As[tr * 33 + k];
            float a1 = As[(tr + 16) * 33 + k];
            float w0 = Bs[k * 33 + tc];
            float w1 = Bs[k * 33 + tc + 16];
            acc00 += a0 * w0; acc01 += a0 * w1;
            acc10 += a1 * w0; acc11 += a1 * w1;
        }
        __syncthreads();
    }
    float bq0 = bq[h0 + tc], bq1 = bq[h0 + tc + 16];
    g_Q[(b0 + tr) * CLIPD + h0 + tc]           = acc00 + bq0;
    g_Q[(b0 + tr) * CLIPD + h0 + tc + 16]      = acc01 + bq1;
    g_Q[(b0 + tr + 16) * CLIPD + h0 + tc]      = acc10 + bq0;
    g_Q[(b0 + tr + 16) * CLIPD + h0 + tc + 16] = acc11 + bq1;
}

// ---------------------------------------------------------------------------
// P2: qk[b,h,j] = (sum_d Q[b, h*64+d] * Wk[j, h*64+d]) / (8*temperature)
// grid (32 b-groups of 4, 8 heads), 384 threads; thread j computes 4 b's,
// sharing each Wk row load 4x (Wk tile stays hot in L1/L2).
// ---------------------------------------------------------------------------
__global__ void __launch_bounds__(384)
k_qk(const float* __restrict__ Wk, const float* __restrict__ temp) {
    __shared__ float Qs[4 * HD];
    const int t  = threadIdx.x;
    const int bg = blockIdx.x;          // 0..31
    const int h  = blockIdx.y;          // 0..7
    if (t < 4 * HD)
        Qs[t] = g_Q[(bg * 4 + (t >> 6)) * CLIPD + h * HD + (t & 63)];
    __syncthreads();

    const float inv_scale = 1.0f / (8.0f * temp[0]);
    const int j = t;                    // 0..383
    const float4* w4 = reinterpret_cast<const float4*>(Wk + (size_t)j * CLIPD + h * HD);
    const float4* q4 = reinterpret_cast<const float4*>(Qs);
    float a0 = 0.f, a1 = 0.f, a2 = 0.f, a3 = 0.f;
    #pragma unroll
    for (int i = 0; i < 16; ++i) {
        float4 w  = w4[i];
        float4 x0 = q4[i], x1 = q4[16 + i], x2 = q4[32 + i], x3 = q4[48 + i];
        a0 += w.x * x0.x + w.y * x0.y + w.z * x0.z + w.w * x0.w;
        a1 += w.x * x1.x + w.y * x1.y + w.z * x1.z + w.w * x1.w;
        a2 += w.x * x2.x + w.y * x2.y + w.z * x2.z + w.w * x2.w;
        a3 += w.x * x3.x + w.y * x3.y + w.z * x3.z + w.w * x3.w;
    }
    g_qk[((size_t)(bg * 4 + 0) * NH + h) * DINOD + j] = a0 * inv_scale;
    g_qk[((size_t)(bg * 4 + 1) * NH + h) * DINOD + j] = a1 * inv_scale;
    g_qk[((size_t)(bg * 4 + 2) * NH + h) * DINOD + j] = a2 * inv_scale;
    g_qk[((size_t)(bg * 4 + 3) * NH + h) * DINOD + j] = a3 * inv_scale;
}

// ---------------------------------------------------------------------------
// Main: per-b flash attention over N=1369 with 384-dim ctx accumulators,
// fused ctx@Wv + bv + LayerNorm epilogue. grid = 128, 384 threads.
// ---------------------------------------------------------------------------
static __device__ __forceinline__ void issue_tile(const float* __restrict__ dino,
                                                  int b, int tile, float* dst, int t) {
    const int n0 = tile * TN;
    #pragma unroll
    for (int i = 0; i < 12; ++i) {
        int idx = t + i * 384;          // < 4608 = 48 rows * 96 float4
        int row = idx / 96;
        int c4  = idx % 96;
        int n   = n0 + row;
        bool valid = (n < NTOK);
        int nc = valid ? n : (NTOK - 1);                  // clamp addr, zfill data
        const float* src = dino + ((size_t)b * NTOK + nc) * DINOD + c4 * 4;
        cp16(dst + row * DPITCH + c4 * 4, src, valid);
    }
    asm volatile("cp.async.commit_group;\n" ::: "memory");
}

__global__ void __launch_bounds__(384)
k_main(const float* __restrict__ dino, const float* __restrict__ Wv,
       const float* __restrict__ bv, const float* __restrict__ gamma,
       const float* __restrict__ beta, float* __restrict__ out) {
    extern __shared__ float sm[];
    const int b = blockIdx.x;
    const int t = threadIdx.x;
    const int w = t >> 5, l = t & 31;

    float* ds   = sm + OFF_DS;
    float* qks  = sm + OFF_QK;
    float* Lp   = sm + OFF_LP;
    float* ps   = sm + OFF_PS;
    float* outs = sm + OFF_OUTS;
    float* mrun = sm + OFF_MRUN;
    float* lrun = sm + OFF_LRUN;
    float* alph = sm + OFF_ALPH;
    float* red  = sm + OFF_RED;
    float* red2 = sm + OFF_RED2;
    float* stat = sm + OFF_STAT;

    // init: stage qk rows for this b, init running stats
    for (int i = t; i < NH * DINOD; i += 384)
        qks[(i / DINOD) * QPITCH + (i % DINOD)] = g_qk[(size_t)b * NH * DINOD + i];
    if (t < NH) { mrun[t] = -3.0e38f; lrun[t] = 0.f; }

    float ctx[NH];
    #pragma unroll
    for (int h = 0; h < NH; ++h) ctx[h] = 0.f;

    issue_tile(dino, b, 0, ds, t);

    // phase-2 thread decomposition: 16 n-groups (3 tokens) x 24 j-splits (16 j)
    const int gn = l & 15;
    const int gj = (w << 1) | (l >> 4);
    const int j0 = gj * 16;

    for (int tt = 0; tt < NT; ++tt) {
        const float* dsb = ds + (tt & 1) * TN * DPITCH;
        if (tt + 1 < NT) {
            issue_tile(dino, b, tt + 1, ds + ((tt + 1) & 1) * TN * DPITCH, t);
            asm volatile("cp.async.wait_group 1;\n" ::: "memory");
        } else {
            asm volatile("cp.async.wait_group 0;\n" ::: "memory");
        }
        __syncthreads();   // tile tt visible to all threads

        // ---- phase 2: logits partials  C[8h][48n] over j-chunk of 16
        float acc[NH][3];
        #pragma unroll
        for (int h = 0; h < NH; ++h)
            #pragma unroll
            for (int k = 0; k < 3; ++k) acc[h][k] = 0.f;

        #pragma unroll
        for (int jj = 0; jj < 4; ++jj) {
            const int jc = j0 + jj * 4;
            float4 a[NH];
            #pragma unroll
            for (int h = 0; h < NH; ++h)
                a[h] = *reinterpret_cast<const float4*>(&qks[h * QPITCH + jc]);
            #pragma unroll
            for (int k = 0; k < 3; ++k) {
                float4 d4 = *reinterpret_cast<const float4*>(&dsb[(gn * 3 + k) * DPITCH + jc]);
                #pragma unroll
                for (int h = 0; h < NH; ++h)
                    acc[h][k] += a[h].x * d4.x + a[h].y * d4.y + a[h].z * d4.z + a[h].w * d4.w;
            }
        }
        // pair-combine (gj, gj+1) within warp -> 12 smem partials
        #pragma unroll
        for (int h = 0; h < NH; ++h)
            #pragma unroll
            for (int k = 0; k < 3; ++k) {
                float v = acc[h][k] + __shfl_down_sync(0xffffffffu, acc[h][k], 16);
                if (l < 16) Lp[(w * NH + h) * TN + gn * 3 + k] = v;
            }
        __syncthreads();

        // ---- softmax (warp h owns head h; reduces 12 partials itself)
        if (w < NH) {
            const int h = w;
            const int valid = (tt == NT - 1) ? (NTOK - (NT - 1) * TN) : TN;
            float v0 = 0.f;
            #pragma unroll
            for (int s = 0; s < 12; ++s) v0 += Lp[(s * NH + h) * TN + l];
            float v1 = -3.0e38f;
            if (l < 16) {
                float x = 0.f;
                #pragma unroll
                for (int s = 0; s < 12; ++s) x += Lp[(s * NH + h) * TN + l + 32];
                v1 = x;
            }
            if (l >= valid) v0 = -3.0e38f;
            if (l < 16 && l + 32 >= valid) v1 = -3.0e38f;

            float m = fmaxf(v0, v1);
            #pragma unroll
            for (int o = 16; o > 0; o >>= 1)
                m = fmaxf(m, __shfl_xor_sync(0xffffffffu, m, o));
            float mold = mrun[h];
            float mnew = fmaxf(mold, m);

            float p0 = (l < valid) ? __expf(v0 - mnew) : 0.f;
            float p1 = (l < 16 && l + 32 < valid) ? __expf(v1 - mnew) : 0.f;
            ps[h * PSP + l] = p0;
            if (l < 16) ps[h * PSP + l + 32] = p1;
            float s = p0 + p1;
            #pragma unroll
            for (int o = 16; o > 0; o >>= 1)
                s += __shfl_xor_sync(0xffffffffu, s, o);
            if (l == 0) {
                float al = __expf(mold - mnew);
                alph[h] = al;
                lrun[h] = lrun[h] * al + s;
                mrun[h] = mnew;
            }
        }
        __syncthreads();

        // ---- phase 3: rank-48 ctx update; thread owns column j = t
        #pragma unroll
        for (int h = 0; h < NH; ++h) ctx[h] *= alph[h];
        #pragma unroll
        for (int n4 = 0; n4 < 12; ++n4) {
            float4 p4[NH];
            #pragma unroll
            for (int h = 0; h < NH; ++h)
                p4[h] = *reinterpret_cast<const float4*>(&ps[h * PSP + n4 * 4]);
            #pragma unroll
            for (int k = 0; k < 4; ++k) {
                float d = dsb[(n4 * 4 + k) * DPITCH + t];
                #pragma unroll
                for (int h = 0; h < NH; ++h) {
                    float pv = (k == 0) ? p4[h].x : (k == 1) ? p4[h].y
                             : (k == 2) ? p4[h].z : p4[h].w;
                    ctx[h] += pv * d;
                }
            }
        }
        __syncthreads();   // phase-3 reads done before next overwrite of this buf
    }

    // ---- epilogue: out = (ctx/l) @ Wv + bv, then LayerNorm
    #pragma unroll
    for (int h = 0; h < NH; ++h)
        sm[h * DPITCH + t] = ctx[h] / lrun[h];   // ctxs overlays ds buffer
    __syncthreads();

    for (int c = t; c < CLIPD; c += 384) {
        const int h = c >> 6;
        const float* crow = sm + h * DPITCH;
        const float* wcol = Wv + c;
        float a0 = 0.f, a1 = 0.f, a2 = 0.f, a3 = 0.f;
        #pragma unroll 4
        for (int jx = 0; jx < DINOD; jx += 4) {
            a0 += crow[jx]     * wcol[(size_t)jx * CLIPD];
            a1 += crow[jx + 1] * wcol[(size_t)(jx + 1) * CLIPD];
            a2 += crow[jx + 2] * wcol[(size_t)(jx + 2) * CLIPD];
            a3 += crow[jx + 3] * wcol[(size_t)(jx + 3) * CLIPD];
        }
        outs[c] = a0 + a1 + a2 + a3 + bv[c];
    }
    __syncthreads();

    float s = 0.f, s2 = 0.f;
    for (int c = t; c < CLIPD; c += 384) { float v = outs[c]; s += v; s2 += v * v; }
    #pragma unroll
    for (int o = 16; o > 0; o >>= 1) {
        s  += __shfl_xor_sync(0xffffffffu, s, o);
        s2 += __shfl_xor_sync(0xffffffffu, s2, o);
    }
    if (l == 0) { red[w] = s; red2[w] = s2; }
    __syncthreads();
    if (t == 0) {
        float ss = 0.f, ss2 = 0.f;
        for (int i = 0; i < 12; ++i) { ss += red[i]; ss2 += red2[i]; }
        float mu  = ss / 512.f;
        float var = ss2 / 512.f - mu * mu;
        stat[0] = mu;
        stat[1] = rsqrtf(var + 1e-5f);
    }
    __syncthreads();
    float mu = stat[0], rs = stat[1];
    for (int c = t; c < CLIPD; c += 384)
        out[(size_t)b * CLIPD + c] = (outs[c] - mu) * rs * gamma[c] + beta[c];
}

// ---------------------------------------------------------------------------
extern "C" void kernel_launch(void* const* d_in, const int* in_sizes, int n_in,
                              void* d_out, int out_size) {
    const float* dino  = (const float*)d_in[0];
    const float* clip  = (const float*)d_in[1];
    const float* Wq    = (const float*)d_in[2];
    const float* bq    = (const float*)d_in[3];
    const float* Wk    = (const float*)d_in[4];
    // d_in[5] = bk: cancels in softmax (constant per (b,h))
    const float* Wv    = (const float*)d_in[6];
    const float* bv    = (const float*)d_in[7];
    const float* temp  = (const float*)d_in[8];
    const float* gamma = (const float*)d_in[9];
    const float* beta  = (const float*)d_in[10];
    float* out = (float*)d_out;
    (void)in_sizes; (void)n_in; (void)out_size;

    cudaFuncSetAttribute(k_main, cudaFuncAttributeMaxDynamicSharedMemorySize, SMEM_BYTES);

    k_qproj<<<dim3(16, 4), 256>>>(clip, Wq, bq);
    k_qk<<<dim3(32, 8), 384>>>(Wk, temp);
    k_main<<<NB, 384, SMEM_BYTES>>>(dino, Wv, bv, gamma, beta, out);
}

// round 10
// speedup vs baseline: 1.0340x; 1.0340x over previous
#include <cuda_runtime.h>
#include <cstdint>
#include <cstddef>

// ---------------------------------------------------------------- constants
#define NB     128
#define NTOK   1369
#define DINOD  384
#define CLIPD  512
#define NH     8
#define HD     64
#define TN     48          // tokens per tile
#define NT     29          // ceil(1369/48)
#define DPITCH 388         // dino tile row pitch (floats): 16B-aligned, bank-skewed
#define QPITCH 392         // qk row pitch (16B-aligned)
#define PSP    52          // p row pitch (52*4=208 B, 16B-aligned)

// dynamic smem layout for k_main (float offsets)
#define OFF_DS   0
#define OFF_QK   (2*TN*DPITCH)            // 37248
#define OFF_LP   (OFF_QK + NH*QPITCH)     // 40384
#define OFF_PS   (OFF_LP + 12*NH*TN)      // 44992
#define OFF_OUTS (OFF_PS + NH*PSP)        // 45408
#define OFF_MRUN (OFF_OUTS + CLIPD)       // 45920
#define OFF_LRUN (OFF_MRUN + NH)
#define OFF_ALPH (OFF_LRUN + NH)
#define OFF_RED  (OFF_ALPH + NH)
#define OFF_RED2 (OFF_RED + 12)
#define OFF_STAT (OFF_RED2 + 12)
#define SMEM_FLOATS (OFF_STAT + 2)
#define SMEM_BYTES  (SMEM_FLOATS * 4)

// packed fp32x2 ops (Blackwell FFMA2 — only reachable via PTX)
#define FMAF2(d, a, b) \
    asm("fma.rn.f32x2 %0, %1, %2, %0;" : "+l"(d) : "l"(a), "l"(b))
#define MULF2(d, a, b) \
    asm("mul.rn.f32x2 %0, %1, %2;" : "=l"(d) : "l"(a), "l"(b))
#define PACKF2(r, lo, hi) \
    asm("mov.b64 %0, {%1, %2};" : "=l"(r) : "f"(lo), "f"(hi))
#define UNPACKF2(lo, hi, r) \
    asm("mov.b64 {%0, %1}, %2;" : "=f"(lo), "=f"(hi) : "l"(r))

// device scratch (no allocation APIs allowed)
__device__ float g_qk[NB * NH * DINOD];

static __device__ __forceinline__ void cp16(float* sdst, const float* gsrc, bool valid) {
    uint32_t s = (uint32_t)__cvta_generic_to_shared(sdst);
    int sz = valid ? 16 : 0;     // sz=0 -> zero-fill destination
    asm volatile("cp.async.cg.shared.global [%0], [%1], 16, %2;\n"
                 :: "r"(s), "l"(gsrc), "r"(sz) : "memory");
}

// ---------------------------------------------------------------------------
// Fused prep: per (b-group of 4, head) block
//   stage A: Q[bi, d] = clip[b,:] @ Wq[:, h*64+d] + bq[h*64+d]   (4x64 slice)
//   stage B: qk[b,h,j] = Q[bi,:] . Wk[j, h*64:...] / (8*temperature)
// grid (32, 8), 384 threads.
// ---------------------------------------------------------------------------
__global__ void __launch_bounds__(384)
k_prep(const float* __restrict__ clip, const float* __restrict__ Wq,
       const float* __restrict__ bq, const float* __restrict__ Wk,
       const float* __restrict__ temp) {
    __shared__ float clips[4 * CLIPD];
    __shared__ float Qs[4 * HD];
    const int t  = threadIdx.x;
    const int bg = blockIdx.x;          // 0..31
    const int h  = blockIdx.y;          // 0..7

    for (int i = t; i < 4 * CLIPD; i += 384)
        clips[i] = clip[(bg * 4 + (i >> 9)) * CLIPD + (i & 511)];
    __syncthreads();

    if (t < 256) {
        const int bi = t >> 6, d = t & 63;
        const float* wcol = Wq + h * HD + d;
        const float* cr   = clips + bi * CLIPD;
        float a0 = 0.f, a1 = 0.f, a2 = 0.f, a3 = 0.f;
        #pragma unroll 2
        for (int k = 0; k < CLIPD; k += 4) {
            a0 += cr[k]     * wcol[(size_t)k * CLIPD];
            a1 += cr[k + 1] * wcol[(size_t)(k + 1) * CLIPD];
            a2 += cr[k + 2] * wcol[(size_t)(k + 2) * CLIPD];
            a3 += cr[k + 3] * wcol[(size_t)(k + 3) * CLIPD];
        }
        Qs[t] = a0 + a1 + a2 + a3 + bq[h * HD + d];
    }
    __syncthreads();

    // stage B: thread j computes 4 b's, sharing each Wk row load 4x
    const float inv_scale = 1.0f / (8.0f * temp[0]);
    const int j = t;                    // 0..383
    const float4* w4 = reinterpret_cast<const float4*>(Wk + (size_t)j * CLIPD + h * HD);
    const float4* q4 = reinterpret_cast<const float4*>(Qs);
    float a0 = 0.f, a1 = 0.f, a2 = 0.f, a3 = 0.f;
    #pragma unroll
    for (int i = 0; i < 16; ++i) {
        float4 w  = w4[i];
        float4 x0 = q4[i], x1 = q4[16 + i], x2 = q4[32 + i], x3 = q4[48 + i];
        a0 += w.x * x0.x + w.y * x0.y + w.z * x0.z + w.w * x0.w;
        a1 += w.x * x1.x + w.y * x1.y + w.z * x1.z + w.w * x1.w;
        a2 += w.x * x2.x + w.y * x2.y + w.z * x2.z + w.w * x2.w;
        a3 += w.x * x3.x + w.y * x3.y + w.z * x3.z + w.w * x3.w;
    }
    g_qk[((size_t)(bg * 4 + 0) * NH + h) * DINOD + j] = a0 * inv_scale;
    g_qk[((size_t)(bg * 4 + 1) * NH + h) * DINOD + j] = a1 * inv_scale;
    g_qk[((size_t)(bg * 4 + 2) * NH + h) * DINOD + j] = a2 * inv_scale;
    g_qk[((size_t)(bg * 4 + 3) * NH + h) * DINOD + j] = a3 * inv_scale;
}

// ---------------------------------------------------------------------------
// Main: per-b flash attention over N=1369 with 384-dim ctx accumulators,
// fused ctx@Wv + bv + LayerNorm epilogue. grid = 128, 384 threads.
// ---------------------------------------------------------------------------
static __device__ __forceinline__ void issue_tile(const float* __restrict__ dino,
                                                  int b, int tile, float* dst, int t) {
    const int n0 = tile * TN;
    #pragma unroll
    for (int i = 0; i < 12; ++i) {
        int idx = t + i * 384;          // < 4608 = 48 rows * 96 float4
        int row = idx / 96;
        int c4  = idx % 96;
        int n   = n0 + row;
        bool valid = (n < NTOK);
        int nc = valid ? n : (NTOK - 1);                  // clamp addr, zfill data
        const float* src = dino + ((size_t)b * NTOK + nc) * DINOD + c4 * 4;
        cp16(dst + row * DPITCH + c4 * 4, src, valid);
    }
    asm volatile("cp.async.commit_group;\n" ::: "memory");
}

__global__ void __launch_bounds__(384)
k_main(const float* __restrict__ dino, const float* __restrict__ Wv,
       const float* __restrict__ bv, const float* __restrict__ gamma,
       const float* __restrict__ beta, float* __restrict__ out) {
    extern __shared__ float sm[];
    const int b = blockIdx.x;
    const int t = threadIdx.x;
    const int w = t >> 5, l = t & 31;

    float* ds   = sm + OFF_DS;
    float* qks  = sm + OFF_QK;
    float* Lp   = sm + OFF_LP;
    float* ps   = sm + OFF_PS;
    float* outs = sm + OFF_OUTS;
    float* mrun = sm + OFF_MRUN;
    float* lrun = sm + OFF_LRUN;
    float* alph = sm + OFF_ALPH;
    float* red  = sm + OFF_RED;
    float* red2 = sm + OFF_RED2;
    float* stat = sm + OFF_STAT;

    // init: stage qk rows for this b, init running stats
    for (int i = t; i < NH * DINOD; i += 384)
        qks[(i / DINOD) * QPITCH + (i % DINOD)] = g_qk[(size_t)b * NH * DINOD + i];
    if (t < NH) { mrun[t] = -3.0e38f; lrun[t] = 0.f; }

    // packed ctx accumulators: lane0 = even-n partial, lane1 = odd-n partial
    unsigned long long ctx2[NH];
    #pragma unroll
    for (int h = 0; h < NH; ++h) ctx2[h] = 0ull;

    issue_tile(dino, b, 0, ds, t);

    // phase-2 decomposition: 16 n-groups (3 tokens) x 24 j-splits (16 j)
    const int gn = l & 15;
    const int gj = (w << 1) | (l >> 4);
    const int j0 = gj * 16;

    for (int tt = 0; tt < NT; ++tt) {
        const float* dsb = ds + (tt & 1) * TN * DPITCH;
        if (tt + 1 < NT) {
            issue_tile(dino, b, tt + 1, ds + ((tt + 1) & 1) * TN * DPITCH, t);
            asm volatile("cp.async.wait_group 1;\n" ::: "memory");
        } else {
            asm volatile("cp.async.wait_group 0;\n" ::: "memory");
        }
        __syncthreads();   // tile tt visible to all threads

        // ---- phase 2: logits partials C[8h][48n] over j-chunk of 16 (packed fp32x2)
        unsigned long long acc2[NH][3];
        #pragma unroll
        for (int h = 0; h < NH; ++h)
            #pragma unroll
            for (int k = 0; k < 3; ++k) acc2[h][k] = 0ull;

        #pragma unroll
        for (int jj = 0; jj < 4; ++jj) {
            const int jc = j0 + jj * 4;
            ulonglong2 a2[NH];
            #pragma unroll
            for (int h = 0; h < NH; ++h)
                a2[h] = *reinterpret_cast<const ulonglong2*>(&qks[h * QPITCH + jc]);
            #pragma unroll
            for (int k = 0; k < 3; ++k) {
                ulonglong2 d2 = *reinterpret_cast<const ulonglong2*>(&dsb[(gn * 3 + k) * DPITCH + jc]);
                #pragma unroll
                for (int h = 0; h < NH; ++h) {
                    FMAF2(acc2[h][k], a2[h].x, d2.x);
                    FMAF2(acc2[h][k], a2[h].y, d2.y);
                }
            }
        }
        // horizontal add + pair-combine (gj, gj+1) within warp -> 12 smem partials
        #pragma unroll
        for (int h = 0; h < NH; ++h)
            #pragma unroll
            for (int k = 0; k < 3; ++k) {
                float lo, hi;
                UNPACKF2(lo, hi, acc2[h][k]);
                float v = lo + hi;
                v += __shfl_down_sync(0xffffffffu, v, 16);
                if (l < 16) Lp[(w * NH + h) * TN + gn * 3 + k] = v;
            }
        __syncthreads();

        // ---- softmax (warp h owns head h; reduces 12 partials itself)
        if (w < NH) {
            const int h = w;
            const int valid = (tt == NT - 1) ? (NTOK - (NT - 1) * TN) : TN;
            float v0 = 0.f;
            #pragma unroll
            for (int s = 0; s < 12; ++s) v0 += Lp[(s * NH + h) * TN + l];
            float v1 = -3.0e38f;
            if (l < 16) {
                float x = 0.f;
                #pragma unroll
                for (int s = 0; s < 12; ++s) x += Lp[(s * NH + h) * TN + l + 32];
                v1 = x;
            }
            if (l >= valid) v0 = -3.0e38f;
            if (l < 16 && l + 32 >= valid) v1 = -3.0e38f;

            float m = fmaxf(v0, v1);
            #pragma unroll
            for (int o = 16; o > 0; o >>= 1)
                m = fmaxf(m, __shfl_xor_sync(0xffffffffu, m, o));
            float mold = mrun[h];
            float mnew = fmaxf(mold, m);

            float p0 = (l < valid) ? __expf(v0 - mnew) : 0.f;
            float p1 = (l < 16 && l + 32 < valid) ? __expf(v1 - mnew) : 0.f;
            ps[h * PSP + l] = p0;
            if (l < 16) ps[h * PSP + l + 32] = p1;
            float s = p0 + p1;
            #pragma unroll
            for (int o = 16; o > 0; o >>= 1)
                s += __shfl_xor_sync(0xffffffffu, s, o);
            if (l == 0) {
                float al = __expf(mold - mnew);
                alph[h] = al;
                lrun[h] = lrun[h] * al + s;
                mrun[h] = mnew;
            }
        }
        __syncthreads();

        // ---- phase 3: rank-48 ctx update (packed fp32x2); thread owns column j = t
        #pragma unroll
        for (int h = 0; h < NH; ++h) {
            float al = alph[h];
            unsigned long long aa;
            PACKF2(aa, al, al);
            MULF2(ctx2[h], ctx2[h], aa);
        }
        #pragma unroll
        for (int n4 = 0; n4 < 12; ++n4) {
            ulonglong2 p2[NH];    // .x = (p[n], p[n+1]), .y = (p[n+2], p[n+3])
            #pragma unroll
            for (int h = 0; h < NH; ++h)
                p2[h] = *reinterpret_cast<const ulonglong2*>(&ps[h * PSP + n4 * 4]);
            float d0 = dsb[(n4 * 4 + 0) * DPITCH + t];
            float d1 = dsb[(n4 * 4 + 1) * DPITCH + t];
            float d2 = dsb[(n4 * 4 + 2) * DPITCH + t];
            float d3 = dsb[(n4 * 4 + 3) * DPITCH + t];
            unsigned long long dd01, dd23;
            PACKF2(dd01, d0, d1);
            PACKF2(dd23, d2, d3);
            #pragma unroll
            for (int h = 0; h < NH; ++h) {
                FMAF2(ctx2[h], p2[h].x, dd01);
                FMAF2(ctx2[h], p2[h].y, dd23);
            }
        }
        __syncthreads();   // phase-3 reads done before next overwrite of this buf
    }

    // ---- epilogue: out = (ctx/l) @ Wv + bv, then LayerNorm
    #pragma unroll
    for (int h = 0; h < NH; ++h) {
        float lo, hi;
        UNPACKF2(lo, hi, ctx2[h]);
        sm[h * DPITCH + t] = (lo + hi) / lrun[h];   // ctx overlays ds buffer
    }
    __syncthreads();

    for (int c = t; c < CLIPD; c += 384) {
        const int h = c >> 6;
        const float* crow = sm + h * DPITCH;
        const float* wcol = Wv + c;
        float a0 = 0.f, a1 = 0.f, a2 = 0.f, a3 = 0.f;
        #pragma unroll 4
        for (int jx = 0; jx < DINOD; jx += 4) {
            a0 += crow[jx]     * wcol[(size_t)jx * CLIPD];
            a1 += crow[jx + 1] * wcol[(size_t)(jx + 1) * CLIPD];
            a2 += crow[jx + 2] * wcol[(size_t)(jx + 2) * CLIPD];
            a3 += crow[jx + 3] * wcol[(size_t)(jx + 3) * CLIPD];
        }
        outs[c] = a0 + a1 + a2 + a3 + bv[c];
    }
    __syncthreads();

    float s = 0.f, s2 = 0.f;
    for (int c = t; c < CLIPD; c += 384) { float v = outs[c]; s += v; s2 += v * v; }
    #pragma unroll
    for (int o = 16; o > 0; o >>= 1) {
        s  += __shfl_xor_sync(0xffffffffu, s, o);
        s2 += __shfl_xor_sync(0xffffffffu, s2, o);
    }
    if (l == 0) { red[w] = s; red2[w] = s2; }
    __syncthreads();
    if (t == 0) {
        float ss = 0.f, ss2 = 0.f;
        for (int i = 0; i < 12; ++i) { ss += red[i]; ss2 += red2[i]; }
        float mu  = ss / 512.f;
        float var = ss2 / 512.f - mu * mu;
        stat[0] = mu;
        stat[1] = rsqrtf(var + 1e-5f);
    }
    __syncthreads();
    float mu = stat[0], rs = stat[1];
    for (int c = t; c < CLIPD; c += 384)
        out[(size_t)b * CLIPD + c] = (outs[c] - mu) * rs * gamma[c] + beta[c];
}

// ---------------------------------------------------------------------------
extern "C" void kernel_launch(void* const* d_in, const int* in_sizes, int n_in,
                              void* d_out, int out_size) {
    const float* dino  = (const float*)d_in[0];
    const float* clip  = (const float*)d_in[1];
    const float* Wq    = (const float*)d_in[2];
    const float* bq    = (const float*)d_in[3];
    const float* Wk    = (const float*)d_in[4];
    // d_in[5] = bk: cancels in softmax (constant per (b,h))
    const float* Wv    = (const float*)d_in[6];
    const float* bv    = (const float*)d_in[7];
    const float* temp  = (const float*)d_in[8];
    const float* gamma = (const float*)d_in[9];
    const float* beta  = (const float*)d_in[10];
    float* out = (float*)d_out;
    (void)in_sizes; (void)n_in; (void)out_size;

    cudaFuncSetAttribute(k_main, cudaFuncAttributeMaxDynamicSharedMemorySize, SMEM_BYTES);

    k_prep<<<dim3(32, 8), 384>>>(clip, Wq, bq, Wk, temp);
    k_main<<<NB, 384, SMEM_BYTES>>>(dino, Wv, bv, gamma, beta, out);
}